// round 2
// baseline (speedup 1.0000x reference)
#include <cuda_runtime.h>
#include <cstdint>

// Problem constants (fixed shapes for this problem instance)
#define D_IN      128
#define E_DIM     64
#define TOTAL     320      // 2*D_IN + E_DIM
#define HEADS     8
#define MAX_NODES 100000

// ---- scratch (no allocations allowed; __device__ globals are the sanctioned path) ----
__device__ float g_weff_node[256 * HEADS];   // Weff rows 0..255, layout [d][h]
__device__ float g_weffT_e[HEADS * E_DIM];   // Weff rows 256..319, TRANSPOSED: [h][k]
__device__ float g_beff[HEADS];              // b1 @ W2 + b2
__device__ float g_proj[MAX_NODES * 16];     // per-node: 8 origin-proj + 8 dest-proj

// ============================================================================
// Kernel 1: Weff = W1 @ W2  (320x8), beff = b1 @ W2 + b2.   One warp per output.
// ============================================================================
__global__ void prep_kernel(const float* __restrict__ W1, const float* __restrict__ b1,
                            const float* __restrict__ W2, const float* __restrict__ b2) {
    int w    = (blockIdx.x * blockDim.x + threadIdx.x) >> 5;
    int lane = threadIdx.x & 31;
    if (w >= TOTAL * HEADS + HEADS) return;

    float s = 0.0f;
    if (w < TOTAL * HEADS) {
        int i = w >> 3;      // Weff row (0..319)
        int h = w & 7;       // head
        #pragma unroll
        for (int t = 0; t < 10; t++) {
            int j = lane + 32 * t;
            s += W1[i * TOTAL + j] * W2[j * HEADS + h];
        }
        #pragma unroll
        for (int o = 16; o > 0; o >>= 1) s += __shfl_down_sync(0xffffffffu, s, o);
        if (lane == 0) {
            if (i < 256) g_weff_node[i * HEADS + h] = s;
            else         g_weffT_e[h * E_DIM + (i - 256)] = s;
        }
    } else {
        int h = w - TOTAL * HEADS;
        #pragma unroll
        for (int t = 0; t < 10; t++) {
            int j = lane + 32 * t;
            s += b1[j] * W2[j * HEADS + h];
        }
        #pragma unroll
        for (int o = 16; o > 0; o >>= 1) s += __shfl_down_sync(0xffffffffu, s, o);
        if (lane == 0) g_beff[h] = s + b2[h];
    }
}

// ============================================================================
// Kernel 2: per-node projections.  One thread per node.
//   proj[n][0:8]  = x[n] @ Weff[0:128]     (origin part)
//   proj[n][8:16] = x[n] @ Weff[128:256]   (dest part)
// ============================================================================
__global__ __launch_bounds__(256) void node_proj_kernel(const float* __restrict__ x,
                                                        int n_nodes) {
    __shared__ float sw[256 * HEADS];   // 8 KB
    for (int i = threadIdx.x; i < 256 * HEADS; i += blockDim.x) sw[i] = g_weff_node[i];
    __syncthreads();

    int n = blockIdx.x * blockDim.x + threadIdx.x;
    if (n >= n_nodes) return;

    float acc_o[8], acc_d[8];
    #pragma unroll
    for (int h = 0; h < 8; h++) { acc_o[h] = 0.0f; acc_d[h] = 0.0f; }

    const float4* xr = reinterpret_cast<const float4*>(x + (size_t)n * D_IN);

    for (int c = 0; c < D_IN / 4; c++) {       // 32 float4 loads
        float4 xv = __ldg(xr + c);
        float xs[4] = {xv.x, xv.y, xv.z, xv.w};
        #pragma unroll
        for (int j = 0; j < 4; j++) {
            int d = 4 * c + j;
            const float4* wo = reinterpret_cast<const float4*>(sw + d * HEADS);
            float4 w0 = wo[0], w1 = wo[1];
            acc_o[0] += xs[j] * w0.x;  acc_o[1] += xs[j] * w0.y;
            acc_o[2] += xs[j] * w0.z;  acc_o[3] += xs[j] * w0.w;
            acc_o[4] += xs[j] * w1.x;  acc_o[5] += xs[j] * w1.y;
            acc_o[6] += xs[j] * w1.z;  acc_o[7] += xs[j] * w1.w;
            const float4* wd = reinterpret_cast<const float4*>(sw + (128 + d) * HEADS);
            float4 v0 = wd[0], v1 = wd[1];
            acc_d[0] += xs[j] * v0.x;  acc_d[1] += xs[j] * v0.y;
            acc_d[2] += xs[j] * v0.z;  acc_d[3] += xs[j] * v0.w;
            acc_d[4] += xs[j] * v1.x;  acc_d[5] += xs[j] * v1.y;
            acc_d[6] += xs[j] * v1.z;  acc_d[7] += xs[j] * v1.w;
        }
    }

    float4* pr = reinterpret_cast<float4*>(g_proj + (size_t)n * 16);
    pr[0] = make_float4(acc_o[0], acc_o[1], acc_o[2], acc_o[3]);
    pr[1] = make_float4(acc_o[4], acc_o[5], acc_o[6], acc_o[7]);
    pr[2] = make_float4(acc_d[0], acc_d[1], acc_d[2], acc_d[3]);
    pr[3] = make_float4(acc_d[4], acc_d[5], acc_d[6], acc_d[7]);
}

// ============================================================================
// Kernel 3: edge pass.  8 threads per edge (one per head), persistent
// grid-stride so the 64-float WeffT row stays register-resident.
//   out[e][h] = ee[e] . WeffT[h] + proj[o][h] + proj[d][8+h] + beff[h]
// edge_index is INT32 (JAX x64 disabled downgrades jnp.int64 -> int32).
// ============================================================================
__global__ __launch_bounds__(256) void edge_kernel(const int* __restrict__ ei,
                                                   const float* __restrict__ ee,
                                                   float* __restrict__ out,
                                                   int n_edges, int n_threads) {
    int tid = blockIdx.x * blockDim.x + threadIdx.x;
    int h   = tid & 7;

    // Load this head's WeffT row (64 floats) into registers once.
    float w[E_DIM];
    const float4* wr = reinterpret_cast<const float4*>(g_weffT_e + h * E_DIM);
    #pragma unroll
    for (int i = 0; i < E_DIM / 4; i++) {
        float4 v = wr[i];
        w[4 * i + 0] = v.x; w[4 * i + 1] = v.y; w[4 * i + 2] = v.z; w[4 * i + 3] = v.w;
    }
    float bh = g_beff[h];

    int stride = n_threads >> 3;
    for (int e = tid >> 3; e < n_edges; e += stride) {
        const float4* er = reinterpret_cast<const float4*>(ee + (size_t)e * E_DIM);
        float acc = 0.0f;
        #pragma unroll
        for (int i = 0; i < E_DIM / 4; i++) {
            float4 v = __ldg(er + i);
            acc += v.x * w[4 * i + 0];
            acc += v.y * w[4 * i + 1];
            acc += v.z * w[4 * i + 2];
            acc += v.w * w[4 * i + 3];
        }
        int o = __ldg(ei + e);
        int d = __ldg(ei + n_edges + e);
        acc += g_proj[(size_t)o * 16 + h] + g_proj[(size_t)d * 16 + 8 + h] + bh;
        out[(size_t)e * HEADS + h] = acc;
    }
}

// ============================================================================
// launcher
// ============================================================================
extern "C" void kernel_launch(void* const* d_in, const int* in_sizes, int n_in,
                              void* d_out, int out_size) {
    const float* x   = (const float*)d_in[0];
    const int*   ei  = (const int*)d_in[1];
    const float* ee  = (const float*)d_in[2];
    const float* W1  = (const float*)d_in[3];
    const float* b1  = (const float*)d_in[4];
    const float* W2  = (const float*)d_in[5];
    const float* b2  = (const float*)d_in[6];
    float*       out = (float*)d_out;

    int n_nodes = in_sizes[0] / D_IN;
    int n_edges = in_sizes[1] / 2;

    // K1: Weff/beff prep — (320*8 + 8) warps
    {
        int warps   = TOTAL * HEADS + HEADS;
        int threads = warps * 32;
        int blocks  = (threads + 255) / 256;
        prep_kernel<<<blocks, 256>>>(W1, b1, W2, b2);
    }

    // K2: node projections — one thread per node
    {
        int blocks = (n_nodes + 255) / 256;
        node_proj_kernel<<<blocks, 256>>>(x, n_nodes);
    }

    // K3: edge pass — persistent, 8 threads per edge
    {
        int blocks    = 1184;             // ~8 blocks/SM
        int threads   = 256;
        int n_threads = blocks * threads;
        edge_kernel<<<blocks, threads>>>(ei, ee, out, n_edges, n_threads);
    }
}